// round 16
// baseline (speedup 1.0000x reference)
#include <cuda_runtime.h>
#include <cuda_bf16.h>
#include <math.h>
#include <stdint.h>

#define BB   32
#define EE   8
#define HW   196
#define NP   224          // padded N (196 -> 224)
#define EPS  1e-5f

typedef unsigned long long ull;
typedef __nv_bfloat16 bf16;

// ---------------- scratch (device globals; no runtime allocation) -------------
__device__ float g_rw[BB * EE];
__device__ float g_pp[BB * 1024 * 8];         // pooling partials (7 n-blocks, pad 8)
__device__ float g_part[2 * BB * 256 * HW];   // split-K partials
__device__ bf16  g_cwh[BB * 256 * 2304];
__device__ bf16  g_cwl[BB * 256 * 2304];
__device__ bf16  g_xth[BB * NP * 1024];
__device__ bf16  g_xtl[BB * NP * 1024];

// ---------------- helpers -------------------------------------------------------
__device__ __forceinline__ void cp16(void* s, const void* g) {
    unsigned a = (unsigned)__cvta_generic_to_shared(s);
    asm volatile("cp.async.cg.shared.global [%0], [%1], 16;" :: "r"(a), "l"(g));
}
#define CP_COMMIT() asm volatile("cp.async.commit_group;" ::: "memory")

__device__ __forceinline__ uint32_t smem_u32(const void* p) {
    return (uint32_t)__cvta_generic_to_shared(p);
}
__device__ __forceinline__ void ldsm_x4(uint32_t* r, uint32_t a) {
    asm volatile("ldmatrix.sync.aligned.m8n8.x4.shared.b16 {%0,%1,%2,%3}, [%4];"
                 : "=r"(r[0]), "=r"(r[1]), "=r"(r[2]), "=r"(r[3]) : "r"(a));
}
__device__ __forceinline__ void mma_bf16(float* d, const uint32_t* a, const uint32_t* b) {
    asm volatile("mma.sync.aligned.m16n8k16.row.col.f32.bf16.bf16.f32 "
                 "{%0,%1,%2,%3}, {%4,%5,%6,%7}, {%8,%9}, {%0,%1,%2,%3};"
                 : "+f"(d[0]), "+f"(d[1]), "+f"(d[2]), "+f"(d[3])
                 : "r"(a[0]), "r"(a[1]), "r"(a[2]), "r"(a[3]), "r"(b[0]), "r"(b[1]));
}
__device__ __forceinline__ uint32_t pack_bf16x2(float lo, float hi) {
    uint32_t r;
    asm("cvt.rn.bf16x2.f32 %0, %1, %2;" : "=r"(r) : "f"(hi), "f"(lo));
    return r;
}

// ---------------- routing from pool partials (8-padded, 7 valid) ----------------
__global__ void route_pp_kernel(const float* __restrict__ PP, const float* __restrict__ Wr,
                                const float* __restrict__ br, float* __restrict__ RW, int C)
{
    int b = blockIdx.x, e = threadIdx.x >> 5, lane = threadIdx.x & 31;
    float s = 0.f;
    for (int c = lane; c < C; c += 32) {
        const float* p = PP + ((size_t)b * C + c) * 8;
        float pv = (p[0] + p[1] + p[2] + p[3] + p[4] + p[5] + p[6]) * (1.0f / HW);
        s += pv * Wr[c * EE + e];
    }
    #pragma unroll
    for (int o = 16; o; o >>= 1) s += __shfl_down_sync(0xffffffffu, s, o);
    if (lane == 0) RW[b * EE + e] = 1.0f / (1.0f + expf(-(s + br[e])));
}

// ---------------- combine (K-major) -> bf16 hi/lo, vectorized 8B stores ---------
__global__ void combine_bf16_kernel(const float* __restrict__ Wexp, const float* __restrict__ RW,
                                    bf16* __restrict__ CWh, bf16* __restrict__ CWl, int Wsz)
{
    __shared__ float rws[BB * EE];
    if (threadIdx.x < BB * EE) rws[threadIdx.x] = RW[threadIdx.x];
    __syncthreads();
    int idx = blockIdx.x * blockDim.x + threadIdx.x;
    if (idx >= Wsz / 4) return;
    float4 we[EE];
    #pragma unroll
    for (int e = 0; e < EE; e++) we[e] = ((const float4*)Wexp)[(size_t)e * (Wsz / 4) + idx];
    #pragma unroll 4
    for (int b = 0; b < BB; b++) {
        float4 a = make_float4(0.f, 0.f, 0.f, 0.f);
        #pragma unroll
        for (int e = 0; e < EE; e++) {
            float r = rws[b * EE + e];
            a.x = fmaf(r, we[e].x, a.x); a.y = fmaf(r, we[e].y, a.y);
            a.z = fmaf(r, we[e].z, a.z); a.w = fmaf(r, we[e].w, a.w);
        }
        float h0 = __bfloat162float(__float2bfloat16(a.x));
        float h1 = __bfloat162float(__float2bfloat16(a.y));
        float h2 = __bfloat162float(__float2bfloat16(a.z));
        float h3 = __bfloat162float(__float2bfloat16(a.w));
        uint2 hv, lv;
        hv.x = pack_bf16x2(h0, h1);
        hv.y = pack_bf16x2(h2, h3);
        lv.x = pack_bf16x2(a.x - h0, a.y - h1);
        lv.y = pack_bf16x2(a.z - h2, a.w - h3);
        size_t o4 = ((size_t)b * Wsz) / 4 + idx;
        ((uint2*)CWh)[o4] = hv;
        ((uint2*)CWl)[o4] = lv;
    }
}

// ---------------- combine for stage 2: k = r*256 + c ----------------------------
__global__ void combine2_kernel(const float* __restrict__ W2, const float* __restrict__ RW,
                                bf16* __restrict__ CWh, bf16* __restrict__ CWl)
{
    __shared__ float rws[BB * EE];
    if (threadIdx.x < BB * EE) rws[threadIdx.x] = RW[threadIdx.x];
    __syncthreads();
    int m = blockIdx.x, c = threadIdx.x;
    float w[EE][9];
    #pragma unroll
    for (int e = 0; e < EE; e++)
        #pragma unroll
        for (int r = 0; r < 9; r++)
            w[e][r] = W2[((size_t)e * 256 * 256 + m * 256 + c) * 9 + r];
    for (int b = 0; b < BB; b++) {
        float acc[9];
        #pragma unroll
        for (int r = 0; r < 9; r++) acc[r] = 0.f;
        #pragma unroll
        for (int e = 0; e < EE; e++) {
            float rv = rws[b * EE + e];
            #pragma unroll
            for (int r = 0; r < 9; r++) acc[r] = fmaf(rv, w[e][r], acc[r]);
        }
        size_t base = ((size_t)b * 256 + m) * 2304 + c;
        #pragma unroll
        for (int r = 0; r < 9; r++) {
            bf16 h = __float2bfloat16(acc[r]);
            float l = acc[r] - __bfloat162float(h);
            CWh[base + r * 256] = h;
            CWl[base + r * 256] = __float2bfloat16(l);
        }
    }
}

// ---------------- transpose-convert (+pool partials) ----------------------------
template<bool POOL>
__global__ void transpose_kernel(const float* __restrict__ src,
                                 bf16* __restrict__ dhi, bf16* __restrict__ dlo,
                                 float* __restrict__ pp, int K)
{
    __shared__ float t[32][33];
    int b = blockIdx.z, k0 = blockIdx.x * 32, n0 = blockIdx.y * 32;
    int tx = threadIdx.x, ty = threadIdx.y;
    const float* s = src + (size_t)b * K * HW;
    #pragma unroll
    for (int i = 0; i < 4; i++) {
        int kl = ty + 8 * i, n = n0 + tx;
        float v = (n < HW) ? s[(size_t)(k0 + kl) * HW + n] : 0.f;
        t[kl][tx] = v;
        if (POOL) {
            #pragma unroll
            for (int o = 16; o; o >>= 1) v += __shfl_down_sync(0xffffffffu, v, o);
            if (tx == 0) pp[((size_t)b * K + k0 + kl) * 8 + blockIdx.y] = v;
        }
    }
    __syncthreads();
    #pragma unroll
    for (int i = 0; i < 4; i++) {
        int nl = ty + 8 * i;
        float v = t[tx][nl];
        bf16 h = __float2bfloat16(v);
        float l = v - __bfloat162float(h);
        size_t o = ((size_t)b * NP + (n0 + nl)) * K + k0 + tx;
        dhi[o] = h;
        dlo[o] = __float2bfloat16(l);
    }
}

// ---------------- fused: reduce(splitK) + BN + ReLU + transpose + pool ----------
__global__ void fusedRT_kernel(const float* __restrict__ Part,
                               bf16* __restrict__ dhi, bf16* __restrict__ dlo,
                               float* __restrict__ pp,
                               const float* __restrict__ gam, const float* __restrict__ bet,
                               const float* __restrict__ mu,  const float* __restrict__ var)
{
    __shared__ float t[32][33];
    int b = blockIdx.z, k0 = blockIdx.x * 32, n0 = blockIdx.y * 32;
    int tx = threadIdx.x, ty = threadIdx.y;
    const size_t stride = (size_t)BB * 256 * HW;
    #pragma unroll
    for (int i = 0; i < 4; i++) {
        int kl = ty + 8 * i, c = k0 + kl, n = n0 + tx;
        float inv  = rsqrtf(var[c] + EPS) * gam[c];
        float beta = bet[c] - mu[c] * inv;
        float v = 0.f;
        if (n < HW) {
            size_t o = ((size_t)b * 256 + c) * HW + n;
            v = fmaxf(fmaf(Part[o] + Part[stride + o], inv, beta), 0.f);
        }
        t[kl][tx] = v;
        #pragma unroll
        for (int o = 16; o; o >>= 1) v += __shfl_down_sync(0xffffffffu, v, o);
        if (tx == 0) pp[((size_t)b * 256 + c) * 8 + blockIdx.y] = v;
    }
    __syncthreads();
    #pragma unroll
    for (int i = 0; i < 4; i++) {
        int nl = ty + 8 * i;
        float v = t[tx][nl];
        bf16 h = __float2bfloat16(v);
        float l = v - __bfloat162float(h);
        size_t o = ((size_t)b * NP + (n0 + nl)) * 256 + k0 + tx;
        dhi[o] = h;
        dlo[o] = __float2bfloat16(l);
    }
}

// ---------------- warp-MMA GEMM: 64m x 112n tile, 4 warps, 3-stage depth-2 ------
// 4 warps (2m x 2n); warp tile 32m x 56n (identical proven inner loop).
// 128 threads/CTA, 4 CTAs/SM -> grid 512 runs in ONE wave with 4-way co-tenancy.
#define ROWS24    24
#define ST_AH     0
#define ST_AL     1536
#define ST_BH     3072                     // 128 rows reserved (112 used + pad)
#define ST_BL     6144
#define ST_SIZE   9216                     // bf16 elems per stage
#define NSTAGE    3
#define SMEM_MMA  (NSTAGE * ST_SIZE * 2)   // 55296 bytes

template<bool CONV3, bool FUSE>
__global__ void __launch_bounds__(128, 4)
mma_kernel(const bf16* __restrict__ Ahg, const bf16* __restrict__ Alg,
           const bf16* __restrict__ Bhg, const bf16* __restrict__ Blg,
           float* __restrict__ dst,
           const float* __restrict__ gam, const float* __restrict__ bet,
           const float* __restrict__ mu,  const float* __restrict__ var,
           const float* __restrict__ resid,
           int M_total, int K, int Kc)
{
    extern __shared__ __align__(16) bf16 sm[];

    const int b     = blockIdx.z;
    const int split = blockIdx.y >> 1;
    const int nbase = (blockIdx.y & 1) * 112;
    const int mbase = blockIdx.x * 64;
    const int tid   = threadIdx.x;
    const int wid   = tid >> 5, lane = tid & 31;
    const int wm    = (wid & 1) * 32;
    const int wn    = (wid >> 1) * 56;
    const int kbeg  = split * Kc;
    const int nk    = Kc / 16;

    const bf16* gAh = Ahg + ((size_t)b * M_total + mbase) * K + kbeg;
    const bf16* gAl = Alg + ((size_t)b * M_total + mbase) * K + kbeg;
    const bf16* gBh = CONV3 ? (Bhg + (size_t)b * NP * 256)
                            : (Bhg + ((size_t)b * NP + nbase) * K + kbeg);
    const bf16* gBl = CONV3 ? (Blg + (size_t)b * NP * 256)
                            : (Blg + ((size_t)b * NP + nbase) * K + kbeg);

    float acc[2][7][4];
    #pragma unroll
    for (int s = 0; s < 2; s++)
        #pragma unroll
        for (int t = 0; t < 7; t++)
            #pragma unroll
            for (int i = 0; i < 4; i++) acc[s][t][i] = 0.f;

    auto fill = [&](int kt, int st) {
        bf16* base = sm + st * ST_SIZE;
        const int k0 = kt * 16;
        {   // A: 64 rows x 2 chunks = 128 tasks (one per thread)
            int row = tid >> 1, ch = tid & 1;
            const size_t go = (size_t)row * K + k0 + ch * 8;
            cp16(base + ST_AH + row * ROWS24 + ch * 8, gAh + go);
            cp16(base + ST_AL + row * ROWS24 + ch * 8, gAl + go);
        }
        // B: 112 rows x 2 chunks = 224 tasks over 128 threads
        #pragma unroll
        for (int i = 0; i < 2; i++) {
            int idx = tid + i * 128;
            if (idx < 224) {
                int row = idx >> 1, ch = idx & 1;
                if (!CONV3) {
                    const size_t go = (size_t)row * K + k0 + ch * 8;
                    cp16(base + ST_BH + row * ROWS24 + ch * 8, gBh + go);
                    cp16(base + ST_BL + row * ROWS24 + ch * 8, gBl + go);
                } else {
                    const int ktg = (kbeg >> 4) + kt;
                    const int r  = ktg >> 4;
                    const int c0 = (ktg & 15) << 4;
                    const int n  = nbase + row;
                    const int oy = n / 14, ox = n - 14 * oy;
                    const int iy = oy + r / 3 - 1;
                    const int ix = ox + (r - 3 * (r / 3)) - 1;
                    if (n < HW && (unsigned)iy < 14u && (unsigned)ix < 14u) {
                        const size_t go = (size_t)(iy * 14 + ix) * 256 + c0 + ch * 8;
                        cp16(base + ST_BH + row * ROWS24 + ch * 8, gBh + go);
                        cp16(base + ST_BL + row * ROWS24 + ch * 8, gBl + go);
                    } else {
                        const uint4 z = make_uint4(0, 0, 0, 0);
                        *(uint4*)(base + ST_BH + row * ROWS24 + ch * 8) = z;
                        *(uint4*)(base + ST_BL + row * ROWS24 + ch * 8) = z;
                    }
                }
            }
        }
    };

    // prologue: depth-2 prefetch (R12-proven)
    fill(0, 0); CP_COMMIT();
    if (nk > 1) { fill(1, 1); CP_COMMIT(); }

    // A ldmatrix addressing (16x16 via x4)
    const int lm = lane & 15, lk = lane >> 4;
    // B paired ldmatrix addressing: two n8 tiles + both k-halves in one x4
    const int brow = (lane & 7) + ((lane >> 4) << 3);
    const int bcol = ((lane >> 3) & 1) * 8;

    int st = 0;
    for (int kt = 0; kt < nk; kt++) {
        if (kt + 1 < nk) asm volatile("cp.async.wait_group 1;" ::: "memory");
        else             asm volatile("cp.async.wait_group 0;" ::: "memory");
        __syncthreads();

        bf16* base = sm + st * ST_SIZE;
        uint32_t ah[2][4], al[2][4];
        #pragma unroll
        for (int s = 0; s < 2; s++) {
            ldsm_x4(ah[s], smem_u32(base + ST_AH + (wm + s * 16 + lm) * ROWS24 + lk * 8));
            ldsm_x4(al[s], smem_u32(base + ST_AL + (wm + s * 16 + lm) * ROWS24 + lk * 8));
        }
        uint32_t bh[4][4], bl[4][4];
        #pragma unroll
        for (int p = 0; p < 4; p++) {
            ldsm_x4(bh[p], smem_u32(base + ST_BH + (wn + p * 16 + brow) * ROWS24 + bcol));
            ldsm_x4(bl[p], smem_u32(base + ST_BL + (wn + p * 16 + brow) * ROWS24 + bcol));
        }
        #pragma unroll
        for (int s = 0; s < 2; s++)
            #pragma unroll
            for (int t = 0; t < 7; t++) {
                const int pr = t >> 1, off = (t & 1) * 2;
                mma_bf16(acc[s][t], ah[s], &bh[pr][off]);
                mma_bf16(acc[s][t], ah[s], &bl[pr][off]);
                mma_bf16(acc[s][t], al[s], &bh[pr][off]);
            }

        if (kt + 2 < nk) {
            // stage (st+2)%3 was consumed at iter kt-1; this iter's barrier protects it
            fill(kt + 2, (st + 2 >= 3) ? st - 1 : st + 2);
            CP_COMMIT();
        }
        st = (st + 1 == 3) ? 0 : st + 1;
    }

    // ---- epilogue ----
    const int tm = lane >> 2, tn2 = (lane & 3) * 2;
    if (FUSE) {
        #pragma unroll
        for (int s = 0; s < 2; s++) {
            int r0 = mbase + wm + s * 16 + tm;
            int r1 = r0 + 8;
            float i0 = rsqrtf(var[r0] + EPS) * gam[r0];
            float b0 = bet[r0] - mu[r0] * i0;
            float i1 = rsqrtf(var[r1] + EPS) * gam[r1];
            float b1 = bet[r1] - mu[r1] * i1;
            size_t o0 = ((size_t)b * M_total + r0) * HW;
            size_t o1 = ((size_t)b * M_total + r1) * HW;
            #pragma unroll
            for (int t = 0; t < 7; t++) {
                int n = nbase + wn + t * 8 + tn2;
                if (n < HW) {
                    float2 v0, v1;
                    v0.x = fmaxf(fmaf(acc[s][t][0], i0, b0) + resid[o0 + n],     0.f);
                    v0.y = fmaxf(fmaf(acc[s][t][1], i0, b0) + resid[o0 + n + 1], 0.f);
                    v1.x = fmaxf(fmaf(acc[s][t][2], i1, b1) + resid[o1 + n],     0.f);
                    v1.y = fmaxf(fmaf(acc[s][t][3], i1, b1) + resid[o1 + n + 1], 0.f);
                    *(float2*)(dst + o0 + n) = v0;
                    *(float2*)(dst + o1 + n) = v1;
                }
            }
        }
    } else {
        #pragma unroll
        for (int s = 0; s < 2; s++) {
            int r0 = mbase + wm + s * 16 + tm;
            size_t o0 = (((size_t)split * BB + b) * M_total + r0) * HW;
            size_t o1 = o0 + 8 * HW;
            #pragma unroll
            for (int t = 0; t < 7; t++) {
                int n = nbase + wn + t * 8 + tn2;
                if (n < HW) {
                    *(float2*)(dst + o0 + n) = make_float2(acc[s][t][0], acc[s][t][1]);
                    *(float2*)(dst + o1 + n) = make_float2(acc[s][t][2], acc[s][t][3]);
                }
            }
        }
    }
}

// ------------------------------------------------------------------------------
extern "C" void kernel_launch(void* const* d_in, const int* in_sizes, int n_in,
                              void* d_out, int out_size)
{
    const float* x    = (const float*)d_in[0];
    const float* w1   = (const float*)d_in[1];
    const float* w2   = (const float*)d_in[2];
    const float* w3   = (const float*)d_in[3];
    const float* r1w  = (const float*)d_in[4];
    const float* r1b  = (const float*)d_in[5];
    const float* r2w  = (const float*)d_in[6];
    const float* r2b  = (const float*)d_in[7];
    const float* r3w  = (const float*)d_in[8];
    const float* r3b  = (const float*)d_in[9];
    const float* bn1g = (const float*)d_in[10];
    const float* bn1b = (const float*)d_in[11];
    const float* bn1m = (const float*)d_in[12];
    const float* bn1v = (const float*)d_in[13];
    const float* bn2g = (const float*)d_in[14];
    const float* bn2b = (const float*)d_in[15];
    const float* bn2m = (const float*)d_in[16];
    const float* bn2v = (const float*)d_in[17];
    const float* bn3g = (const float*)d_in[18];
    const float* bn3b = (const float*)d_in[19];
    const float* bn3m = (const float*)d_in[20];
    const float* bn3v = (const float*)d_in[21];
    float* out = (float*)d_out;

    float *rw, *pp, *part;
    bf16 *cwh, *cwl, *xth, *xtl;
    cudaGetSymbolAddress((void**)&rw,   g_rw);
    cudaGetSymbolAddress((void**)&pp,   g_pp);
    cudaGetSymbolAddress((void**)&part, g_part);
    cudaGetSymbolAddress((void**)&cwh,  g_cwh);
    cudaGetSymbolAddress((void**)&cwl,  g_cwl);
    cudaGetSymbolAddress((void**)&xth,  g_xth);
    cudaGetSymbolAddress((void**)&xtl,  g_xtl);

    cudaFuncSetAttribute(mma_kernel<false, false>,
                         cudaFuncAttributeMaxDynamicSharedMemorySize, SMEM_MMA);
    cudaFuncSetAttribute(mma_kernel<true, false>,
                         cudaFuncAttributeMaxDynamicSharedMemorySize, SMEM_MMA);
    cudaFuncSetAttribute(mma_kernel<false, true>,
                         cudaFuncAttributeMaxDynamicSharedMemorySize, SMEM_MMA);

    // ---- stage 1: 1x1, K=1024 -> M=256, split-K=2, grid 512 (one wave) ----
    transpose_kernel<true><<<dim3(1024 / 32, 7, BB), dim3(32, 8)>>>(x, xth, xtl, pp, 1024);
    route_pp_kernel<<<BB, 256>>>(pp, r1w, r1b, rw, 1024);
    combine_bf16_kernel<<<256, 256>>>(w1, rw, cwh, cwl, 256 * 1024);
    mma_kernel<false, false><<<dim3(4, 4, BB), 128, SMEM_MMA>>>(
        cwh, cwl, xth, xtl, part, nullptr, nullptr, nullptr, nullptr, nullptr,
        256, 1024, 512);
    fusedRT_kernel<<<dim3(8, 7, BB), dim3(32, 8)>>>(part, xth, xtl, pp,
                                                    bn1g, bn1b, bn1m, bn1v);

    // ---- stage 2: 3x3 (k = r*256+c), K=2304 -> M=256, split-K=2, grid 512 ----
    route_pp_kernel<<<BB, 256>>>(pp, r2w, r2b, rw, 256);
    combine2_kernel<<<256, 256>>>(w2, rw, cwh, cwl);
    mma_kernel<true, false><<<dim3(4, 4, BB), 128, SMEM_MMA>>>(
        cwh, cwl, xth, xtl, part, nullptr, nullptr, nullptr, nullptr, nullptr,
        256, 2304, 1152);
    fusedRT_kernel<<<dim3(8, 7, BB), dim3(32, 8)>>>(part, xth, xtl, pp,
                                                    bn2g, bn2b, bn2m, bn2v);

    // ---- stage 3: 1x1, K=256 -> M=1024, fused BN+resid+ReLU, grid 1024 ----
    route_pp_kernel<<<BB, 256>>>(pp, r3w, r3b, rw, 256);
    combine_bf16_kernel<<<256, 256>>>(w3, rw, cwh, cwl, 1024 * 256);
    mma_kernel<false, true><<<dim3(16, 2, BB), 128, SMEM_MMA>>>(
        cwh, cwl, xth, xtl, out, bn3g, bn3b, bn3m, bn3v, x, 1024, 256, 256);
}

// round 17
// speedup vs baseline: 1.1026x; 1.1026x over previous
#include <cuda_runtime.h>
#include <cuda_bf16.h>
#include <math.h>
#include <stdint.h>

#define BB   32
#define EE   8
#define HW   196
#define NP   224          // padded N (196 -> 224)
#define EPS  1e-5f

typedef unsigned long long ull;
typedef __nv_bfloat16 bf16;

// ---------------- scratch (device globals; no runtime allocation) -------------
__device__ float g_rw[BB * EE];
__device__ float g_pp[BB * 1024 * 8];         // pooling partials (7 n-blocks, pad 8)
__device__ float g_part[2 * BB * 256 * HW];   // split-K partials
__device__ bf16  g_cwh[BB * 256 * 2304];
__device__ bf16  g_cwl[BB * 256 * 2304];
__device__ bf16  g_xth[BB * NP * 1024];
__device__ bf16  g_xtl[BB * NP * 1024];

// ---------------- helpers -------------------------------------------------------
// PDL: wait for the programmatic-dependency producer (implicit trigger =
// producer completion). No-op when no dependency is outstanding.
#define GDC_WAIT() asm volatile("griddepcontrol.wait;" ::: "memory")

__device__ __forceinline__ void cp16(void* s, const void* g) {
    unsigned a = (unsigned)__cvta_generic_to_shared(s);
    asm volatile("cp.async.cg.shared.global [%0], [%1], 16;" :: "r"(a), "l"(g));
}
#define CP_COMMIT() asm volatile("cp.async.commit_group;" ::: "memory")

__device__ __forceinline__ uint32_t smem_u32(const void* p) {
    return (uint32_t)__cvta_generic_to_shared(p);
}
__device__ __forceinline__ void ldsm_x4(uint32_t* r, uint32_t a) {
    asm volatile("ldmatrix.sync.aligned.m8n8.x4.shared.b16 {%0,%1,%2,%3}, [%4];"
                 : "=r"(r[0]), "=r"(r[1]), "=r"(r[2]), "=r"(r[3]) : "r"(a));
}
__device__ __forceinline__ void mma_bf16(float* d, const uint32_t* a, const uint32_t* b) {
    asm volatile("mma.sync.aligned.m16n8k16.row.col.f32.bf16.bf16.f32 "
                 "{%0,%1,%2,%3}, {%4,%5,%6,%7}, {%8,%9}, {%0,%1,%2,%3};"
                 : "+f"(d[0]), "+f"(d[1]), "+f"(d[2]), "+f"(d[3])
                 : "r"(a[0]), "r"(a[1]), "r"(a[2]), "r"(a[3]), "r"(b[0]), "r"(b[1]));
}
__device__ __forceinline__ uint32_t pack_bf16x2(float lo, float hi) {
    uint32_t r;
    asm("cvt.rn.bf16x2.f32 %0, %1, %2;" : "=r"(r) : "f"(hi), "f"(lo));
    return r;
}

// ---------------- routing from pool partials (8-padded, 7 valid) ----------------
__global__ void route_pp_kernel(const float* __restrict__ PP, const float* __restrict__ Wr,
                                const float* __restrict__ br, float* __restrict__ RW, int C)
{
    GDC_WAIT();
    int b = blockIdx.x, e = threadIdx.x >> 5, lane = threadIdx.x & 31;
    float s = 0.f;
    for (int c = lane; c < C; c += 32) {
        const float* p = PP + ((size_t)b * C + c) * 8;
        float pv = (p[0] + p[1] + p[2] + p[3] + p[4] + p[5] + p[6]) * (1.0f / HW);
        s += pv * Wr[c * EE + e];
    }
    #pragma unroll
    for (int o = 16; o; o >>= 1) s += __shfl_down_sync(0xffffffffu, s, o);
    if (lane == 0) RW[b * EE + e] = 1.0f / (1.0f + expf(-(s + br[e])));
}

// ---------------- combine (K-major) -> bf16 hi/lo, vectorized 8B stores ---------
__global__ void combine_bf16_kernel(const float* __restrict__ Wexp, const float* __restrict__ RW,
                                    bf16* __restrict__ CWh, bf16* __restrict__ CWl, int Wsz)
{
    GDC_WAIT();
    __shared__ float rws[BB * EE];
    if (threadIdx.x < BB * EE) rws[threadIdx.x] = RW[threadIdx.x];
    __syncthreads();
    int idx = blockIdx.x * blockDim.x + threadIdx.x;
    if (idx >= Wsz / 4) return;
    float4 we[EE];
    #pragma unroll
    for (int e = 0; e < EE; e++) we[e] = ((const float4*)Wexp)[(size_t)e * (Wsz / 4) + idx];
    #pragma unroll 4
    for (int b = 0; b < BB; b++) {
        float4 a = make_float4(0.f, 0.f, 0.f, 0.f);
        #pragma unroll
        for (int e = 0; e < EE; e++) {
            float r = rws[b * EE + e];
            a.x = fmaf(r, we[e].x, a.x); a.y = fmaf(r, we[e].y, a.y);
            a.z = fmaf(r, we[e].z, a.z); a.w = fmaf(r, we[e].w, a.w);
        }
        float h0 = __bfloat162float(__float2bfloat16(a.x));
        float h1 = __bfloat162float(__float2bfloat16(a.y));
        float h2 = __bfloat162float(__float2bfloat16(a.z));
        float h3 = __bfloat162float(__float2bfloat16(a.w));
        uint2 hv, lv;
        hv.x = pack_bf16x2(h0, h1);
        hv.y = pack_bf16x2(h2, h3);
        lv.x = pack_bf16x2(a.x - h0, a.y - h1);
        lv.y = pack_bf16x2(a.z - h2, a.w - h3);
        size_t o4 = ((size_t)b * Wsz) / 4 + idx;
        ((uint2*)CWh)[o4] = hv;
        ((uint2*)CWl)[o4] = lv;
    }
}

// ---------------- combine for stage 2: k = r*256 + c ----------------------------
__global__ void combine2_kernel(const float* __restrict__ W2, const float* __restrict__ RW,
                                bf16* __restrict__ CWh, bf16* __restrict__ CWl)
{
    GDC_WAIT();
    __shared__ float rws[BB * EE];
    if (threadIdx.x < BB * EE) rws[threadIdx.x] = RW[threadIdx.x];
    __syncthreads();
    int m = blockIdx.x, c = threadIdx.x;
    float w[EE][9];
    #pragma unroll
    for (int e = 0; e < EE; e++)
        #pragma unroll
        for (int r = 0; r < 9; r++)
            w[e][r] = W2[((size_t)e * 256 * 256 + m * 256 + c) * 9 + r];
    for (int b = 0; b < BB; b++) {
        float acc[9];
        #pragma unroll
        for (int r = 0; r < 9; r++) acc[r] = 0.f;
        #pragma unroll
        for (int e = 0; e < EE; e++) {
            float rv = rws[b * EE + e];
            #pragma unroll
            for (int r = 0; r < 9; r++) acc[r] = fmaf(rv, w[e][r], acc[r]);
        }
        size_t base = ((size_t)b * 256 + m) * 2304 + c;
        #pragma unroll
        for (int r = 0; r < 9; r++) {
            bf16 h = __float2bfloat16(acc[r]);
            float l = acc[r] - __bfloat162float(h);
            CWh[base + r * 256] = h;
            CWl[base + r * 256] = __float2bfloat16(l);
        }
    }
}

// ---------------- transpose-convert (+pool partials) ----------------------------
template<bool POOL>
__global__ void transpose_kernel(const float* __restrict__ src,
                                 bf16* __restrict__ dhi, bf16* __restrict__ dlo,
                                 float* __restrict__ pp, int K)
{
    GDC_WAIT();
    __shared__ float t[32][33];
    int b = blockIdx.z, k0 = blockIdx.x * 32, n0 = blockIdx.y * 32;
    int tx = threadIdx.x, ty = threadIdx.y;
    const float* s = src + (size_t)b * K * HW;
    #pragma unroll
    for (int i = 0; i < 4; i++) {
        int kl = ty + 8 * i, n = n0 + tx;
        float v = (n < HW) ? s[(size_t)(k0 + kl) * HW + n] : 0.f;
        t[kl][tx] = v;
        if (POOL) {
            #pragma unroll
            for (int o = 16; o; o >>= 1) v += __shfl_down_sync(0xffffffffu, v, o);
            if (tx == 0) pp[((size_t)b * K + k0 + kl) * 8 + blockIdx.y] = v;
        }
    }
    __syncthreads();
    #pragma unroll
    for (int i = 0; i < 4; i++) {
        int nl = ty + 8 * i;
        float v = t[tx][nl];
        bf16 h = __float2bfloat16(v);
        float l = v - __bfloat162float(h);
        size_t o = ((size_t)b * NP + (n0 + nl)) * K + k0 + tx;
        dhi[o] = h;
        dlo[o] = __float2bfloat16(l);
    }
}

// ---------------- fused: reduce(splitK) + BN + ReLU + transpose + pool ----------
__global__ void fusedRT_kernel(const float* __restrict__ Part,
                               bf16* __restrict__ dhi, bf16* __restrict__ dlo,
                               float* __restrict__ pp,
                               const float* __restrict__ gam, const float* __restrict__ bet,
                               const float* __restrict__ mu,  const float* __restrict__ var)
{
    GDC_WAIT();
    __shared__ float t[32][33];
    int b = blockIdx.z, k0 = blockIdx.x * 32, n0 = blockIdx.y * 32;
    int tx = threadIdx.x, ty = threadIdx.y;
    const size_t stride = (size_t)BB * 256 * HW;
    #pragma unroll
    for (int i = 0; i < 4; i++) {
        int kl = ty + 8 * i, c = k0 + kl, n = n0 + tx;
        float inv  = rsqrtf(var[c] + EPS) * gam[c];
        float beta = bet[c] - mu[c] * inv;
        float v = 0.f;
        if (n < HW) {
            size_t o = ((size_t)b * 256 + c) * HW + n;
            v = fmaxf(fmaf(Part[o] + Part[stride + o], inv, beta), 0.f);
        }
        t[kl][tx] = v;
        #pragma unroll
        for (int o = 16; o; o >>= 1) v += __shfl_down_sync(0xffffffffu, v, o);
        if (tx == 0) pp[((size_t)b * 256 + c) * 8 + blockIdx.y] = v;
    }
    __syncthreads();
    #pragma unroll
    for (int i = 0; i < 4; i++) {
        int nl = ty + 8 * i;
        float v = t[tx][nl];
        bf16 h = __float2bfloat16(v);
        float l = v - __bfloat162float(h);
        size_t o = ((size_t)b * NP + (n0 + nl)) * 256 + k0 + tx;
        dhi[o] = h;
        dlo[o] = __float2bfloat16(l);
    }
}

// ---------------- warp-MMA GEMM: 128m x 112n tile, 4-stage ring, depth-2 --------
// (R12/R15-proven configuration) 8 warps (4m x 2n); warp tile 32m x 56n.
// B loaded via paired ldmatrix.x4. One barrier per 16-k tile.
#define ROWS24    24
#define ST_AH     0
#define ST_AL     3072
#define ST_BH     6144
#define ST_BL     9216
#define ST_SIZE   12288                    // bf16 elems per stage
#define NSTAGE    4
#define SMEM_MMA  (NSTAGE * ST_SIZE * 2)   // 98304 bytes

template<bool CONV3, bool FUSE>
__global__ void __launch_bounds__(256, 2)
mma_kernel(const bf16* __restrict__ Ahg, const bf16* __restrict__ Alg,
           const bf16* __restrict__ Bhg, const bf16* __restrict__ Blg,
           float* __restrict__ dst,
           const float* __restrict__ gam, const float* __restrict__ bet,
           const float* __restrict__ mu,  const float* __restrict__ var,
           const float* __restrict__ resid,
           int M_total, int K, int Kc)
{
    GDC_WAIT();
    extern __shared__ __align__(16) bf16 sm[];

    const int b     = blockIdx.z;
    const int split = blockIdx.y >> 1;
    const int nbase = (blockIdx.y & 1) * 112;
    const int mbase = blockIdx.x * 128;
    const int tid   = threadIdx.x;
    const int wid   = tid >> 5, lane = tid & 31;
    const int wm    = (wid & 3) * 32;
    const int wn    = (wid >> 2) * 56;
    const int kbeg  = split * Kc;
    const int nk    = Kc / 16;

    const bf16* gAh = Ahg + ((size_t)b * M_total + mbase) * K + kbeg;
    const bf16* gAl = Alg + ((size_t)b * M_total + mbase) * K + kbeg;
    const bf16* gBh = CONV3 ? (Bhg + (size_t)b * NP * 256)
                            : (Bhg + ((size_t)b * NP + nbase) * K + kbeg);
    const bf16* gBl = CONV3 ? (Blg + (size_t)b * NP * 256)
                            : (Blg + ((size_t)b * NP + nbase) * K + kbeg);

    float acc[2][7][4];
    #pragma unroll
    for (int s = 0; s < 2; s++)
        #pragma unroll
        for (int t = 0; t < 7; t++)
            #pragma unroll
            for (int i = 0; i < 4; i++) acc[s][t][i] = 0.f;

    auto fill = [&](int kt, int st) {
        bf16* base = sm + st * ST_SIZE;
        const int k0 = kt * 16;
        {
            int row = tid >> 1, ch = tid & 1;
            const size_t go = (size_t)row * K + k0 + ch * 8;
            cp16(base + ST_AH + row * ROWS24 + ch * 8, gAh + go);
            cp16(base + ST_AL + row * ROWS24 + ch * 8, gAl + go);
        }
        if (tid < 224) {
            int row = tid >> 1, ch = tid & 1;
            if (!CONV3) {
                const size_t go = (size_t)row * K + k0 + ch * 8;
                cp16(base + ST_BH + row * ROWS24 + ch * 8, gBh + go);
                cp16(base + ST_BL + row * ROWS24 + ch * 8, gBl + go);
            } else {
                const int ktg = (kbeg >> 4) + kt;
                const int r  = ktg >> 4;
                const int c0 = (ktg & 15) << 4;
                const int n  = nbase + row;
                const int oy = n / 14, ox = n - 14 * oy;
                const int iy = oy + r / 3 - 1;
                const int ix = ox + (r - 3 * (r / 3)) - 1;
                if (n < HW && (unsigned)iy < 14u && (unsigned)ix < 14u) {
                    const size_t go = (size_t)(iy * 14 + ix) * 256 + c0 + ch * 8;
                    cp16(base + ST_BH + row * ROWS24 + ch * 8, gBh + go);
                    cp16(base + ST_BL + row * ROWS24 + ch * 8, gBl + go);
                } else {
                    const uint4 z = make_uint4(0, 0, 0, 0);
                    *(uint4*)(base + ST_BH + row * ROWS24 + ch * 8) = z;
                    *(uint4*)(base + ST_BL + row * ROWS24 + ch * 8) = z;
                }
            }
        }
    };

    // prologue: prefetch stages 0,1,2 (ring of 4; compute waits at depth 2)
    fill(0, 0); CP_COMMIT();
    if (nk > 1) { fill(1, 1); CP_COMMIT(); }
    if (nk > 2) { fill(2, 2); CP_COMMIT(); }

    // A ldmatrix addressing (16x16 via x4)
    const int lm = lane & 15, lk = lane >> 4;
    // B paired ldmatrix addressing: two n8 tiles + both k-halves in one x4
    const int brow = (lane & 7) + ((lane >> 4) << 3);
    const int bcol = ((lane >> 3) & 1) * 8;

    int st = 0;
    for (int kt = 0; kt < nk; kt++) {
        const int pending = nk - 1 - kt;
        if (pending >= 2)      asm volatile("cp.async.wait_group 2;" ::: "memory");
        else if (pending == 1) asm volatile("cp.async.wait_group 1;" ::: "memory");
        else                   asm volatile("cp.async.wait_group 0;" ::: "memory");
        __syncthreads();

        bf16* base = sm + st * ST_SIZE;
        uint32_t ah[2][4], al[2][4];
        #pragma unroll
        for (int s = 0; s < 2; s++) {
            ldsm_x4(ah[s], smem_u32(base + ST_AH + (wm + s * 16 + lm) * ROWS24 + lk * 8));
            ldsm_x4(al[s], smem_u32(base + ST_AL + (wm + s * 16 + lm) * ROWS24 + lk * 8));
        }
        uint32_t bh[4][4], bl[4][4];
        #pragma unroll
        for (int p = 0; p < 4; p++) {
            ldsm_x4(bh[p], smem_u32(base + ST_BH + (wn + p * 16 + brow) * ROWS24 + bcol));
            ldsm_x4(bl[p], smem_u32(base + ST_BL + (wn + p * 16 + brow) * ROWS24 + bcol));
        }
        #pragma unroll
        for (int s = 0; s < 2; s++)
            #pragma unroll
            for (int t = 0; t < 7; t++) {
                const int pr = t >> 1, off = (t & 1) * 2;
                mma_bf16(acc[s][t], ah[s], &bh[pr][off]);
                mma_bf16(acc[s][t], ah[s], &bl[pr][off]);
                mma_bf16(acc[s][t], al[s], &bh[pr][off]);
            }

        if (kt + 3 < nk) {
            fill(kt + 3, (st + 3) & 3);
            CP_COMMIT();
        }
        st = (st + 1) & 3;
    }

    // ---- epilogue ----
    const int tm = lane >> 2, tn2 = (lane & 3) * 2;
    if (FUSE) {
        #pragma unroll
        for (int s = 0; s < 2; s++) {
            int r0 = mbase + wm + s * 16 + tm;
            int r1 = r0 + 8;
            float i0 = rsqrtf(var[r0] + EPS) * gam[r0];
            float b0 = bet[r0] - mu[r0] * i0;
            float i1 = rsqrtf(var[r1] + EPS) * gam[r1];
            float b1 = bet[r1] - mu[r1] * i1;
            size_t o0 = ((size_t)b * M_total + r0) * HW;
            size_t o1 = ((size_t)b * M_total + r1) * HW;
            #pragma unroll
            for (int t = 0; t < 7; t++) {
                int n = nbase + wn + t * 8 + tn2;
                if (n < HW) {
                    float2 v0, v1;
                    v0.x = fmaxf(fmaf(acc[s][t][0], i0, b0) + resid[o0 + n],     0.f);
                    v0.y = fmaxf(fmaf(acc[s][t][1], i0, b0) + resid[o0 + n + 1], 0.f);
                    v1.x = fmaxf(fmaf(acc[s][t][2], i1, b1) + resid[o1 + n],     0.f);
                    v1.y = fmaxf(fmaf(acc[s][t][3], i1, b1) + resid[o1 + n + 1], 0.f);
                    *(float2*)(dst + o0 + n) = v0;
                    *(float2*)(dst + o1 + n) = v1;
                }
            }
        }
    } else {
        #pragma unroll
        for (int s = 0; s < 2; s++) {
            int r0 = mbase + wm + s * 16 + tm;
            size_t o0 = (((size_t)split * BB + b) * M_total + r0) * HW;
            size_t o1 = o0 + 8 * HW;
            #pragma unroll
            for (int t = 0; t < 7; t++) {
                int n = nbase + wn + t * 8 + tn2;
                if (n < HW) {
                    *(float2*)(dst + o0 + n) = make_float2(acc[s][t][0], acc[s][t][1]);
                    *(float2*)(dst + o1 + n) = make_float2(acc[s][t][2], acc[s][t][3]);
                }
            }
        }
    }
}

// ---------------- PDL launch helper ---------------------------------------------
template<typename F, typename... Args>
static inline void launch_pdl(F f, dim3 g, dim3 blk, size_t smem, Args... args)
{
    cudaLaunchConfig_t cfg = {};
    cfg.gridDim = g;
    cfg.blockDim = blk;
    cfg.dynamicSmemBytes = smem;
    cfg.stream = 0;
    cudaLaunchAttribute attr[1];
    attr[0].id = cudaLaunchAttributeProgrammaticStreamSerialization;
    attr[0].val.programmaticStreamSerializationAllowed = 1;
    cfg.attrs = attr;
    cfg.numAttrs = 1;
    cudaLaunchKernelEx(&cfg, f, args...);
}

// ------------------------------------------------------------------------------
extern "C" void kernel_launch(void* const* d_in, const int* in_sizes, int n_in,
                              void* d_out, int out_size)
{
    const float* x    = (const float*)d_in[0];
    const float* w1   = (const float*)d_in[1];
    const float* w2   = (const float*)d_in[2];
    const float* w3   = (const float*)d_in[3];
    const float* r1w  = (const float*)d_in[4];
    const float* r1b  = (const float*)d_in[5];
    const float* r2w  = (const float*)d_in[6];
    const float* r2b  = (const float*)d_in[7];
    const float* r3w  = (const float*)d_in[8];
    const float* r3b  = (const float*)d_in[9];
    const float* bn1g = (const float*)d_in[10];
    const float* bn1b = (const float*)d_in[11];
    const float* bn1m = (const float*)d_in[12];
    const float* bn1v = (const float*)d_in[13];
    const float* bn2g = (const float*)d_in[14];
    const float* bn2b = (const float*)d_in[15];
    const float* bn2m = (const float*)d_in[16];
    const float* bn2v = (const float*)d_in[17];
    const float* bn3g = (const float*)d_in[18];
    const float* bn3b = (const float*)d_in[19];
    const float* bn3m = (const float*)d_in[20];
    const float* bn3v = (const float*)d_in[21];
    float* out = (float*)d_out;

    float *rw, *pp, *part;
    bf16 *cwh, *cwl, *xth, *xtl;
    cudaGetSymbolAddress((void**)&rw,   g_rw);
    cudaGetSymbolAddress((void**)&pp,   g_pp);
    cudaGetSymbolAddress((void**)&part, g_part);
    cudaGetSymbolAddress((void**)&cwh,  g_cwh);
    cudaGetSymbolAddress((void**)&cwl,  g_cwl);
    cudaGetSymbolAddress((void**)&xth,  g_xth);
    cudaGetSymbolAddress((void**)&xtl,  g_xtl);

    cudaFuncSetAttribute(mma_kernel<false, false>,
                         cudaFuncAttributeMaxDynamicSharedMemorySize, SMEM_MMA);
    cudaFuncSetAttribute(mma_kernel<true, false>,
                         cudaFuncAttributeMaxDynamicSharedMemorySize, SMEM_MMA);
    cudaFuncSetAttribute(mma_kernel<false, true>,
                         cudaFuncAttributeMaxDynamicSharedMemorySize, SMEM_MMA);

    // ---- stage 1: 1x1, K=1024 -> M=256, split-K=2 ----
    launch_pdl(transpose_kernel<true>, dim3(1024 / 32, 7, BB), dim3(32, 8), 0,
               x, xth, xtl, pp, 1024);
    launch_pdl(route_pp_kernel, dim3(BB), dim3(256), 0,
               (const float*)pp, r1w, r1b, rw, 1024);
    launch_pdl(combine_bf16_kernel, dim3(256), dim3(256), 0,
               w1, (const float*)rw, cwh, cwl, 256 * 1024);
    launch_pdl(mma_kernel<false, false>, dim3(2, 4, BB), dim3(256), (size_t)SMEM_MMA,
               (const bf16*)cwh, (const bf16*)cwl, (const bf16*)xth, (const bf16*)xtl,
               part, (const float*)nullptr, (const float*)nullptr,
               (const float*)nullptr, (const float*)nullptr, (const float*)nullptr,
               256, 1024, 512);
    launch_pdl(fusedRT_kernel, dim3(8, 7, BB), dim3(32, 8), 0,
               (const float*)part, xth, xtl, pp, bn1g, bn1b, bn1m, bn1v);

    // ---- stage 2: 3x3 (k = r*256+c), K=2304 -> M=256, split-K=2 ----
    launch_pdl(route_pp_kernel, dim3(BB), dim3(256), 0,
               (const float*)pp, r2w, r2b, rw, 256);
    launch_pdl(combine2_kernel, dim3(256), dim3(256), 0,
               w2, (const float*)rw, cwh, cwl);
    launch_pdl(mma_kernel<true, false>, dim3(2, 4, BB), dim3(256), (size_t)SMEM_MMA,
               (const bf16*)cwh, (const bf16*)cwl, (const bf16*)xth, (const bf16*)xtl,
               part, (const float*)nullptr, (const float*)nullptr,
               (const float*)nullptr, (const float*)nullptr, (const float*)nullptr,
               256, 2304, 1152);
    launch_pdl(fusedRT_kernel, dim3(8, 7, BB), dim3(32, 8), 0,
               (const float*)part, xth, xtl, pp, bn2g, bn2b, bn2m, bn2v);

    // ---- stage 3: 1x1, K=256 -> M=1024, fused BN+resid+ReLU ----
    launch_pdl(route_pp_kernel, dim3(BB), dim3(256), 0,
               (const float*)pp, r3w, r3b, rw, 256);
    launch_pdl(combine_bf16_kernel, dim3(256), dim3(256), 0,
               w3, (const float*)rw, cwh, cwl, 1024 * 256);
    launch_pdl(mma_kernel<false, true>, dim3(8, 2, BB), dim3(256), (size_t)SMEM_MMA,
               (const bf16*)cwh, (const bf16*)cwl, (const bf16*)xth, (const bf16*)xtl,
               out, bn3g, bn3b, bn3m, bn3v, x, 1024, 256, 256);
}